// round 1
// baseline (speedup 1.0000x reference)
#include <cuda_runtime.h>
#include <cuda_bf16.h>
#include <math.h>

// ---------------- problem constants ----------------
#define B_  2
#define S_  2048
#define E_  1024
#define H_  16
#define HD_ 64
#define FF_ 4096
#define M_  (B_ * S_)          // 4096 rows

// ---------------- scratch (static device globals; no allocation) ----------------
__device__ float g_qkv[(size_t)M_ * 3 * E_];   // 4096 x 3072
__device__ float g_ctx[(size_t)M_ * E_];       // 4096 x 1024
__device__ float g_tmp[(size_t)M_ * E_];       // 4096 x 1024
__device__ float g_x1 [(size_t)M_ * E_];       // 4096 x 1024
__device__ float g_h  [(size_t)M_ * FF_];      // 4096 x 4096

// ============================================================================
// GEMM: C[M,N] = A[M,K] @ W[N,K]^T + bias[N], optional exact GELU.
// 128x128 block tile, K-tile 8, 256 threads, 8x8 register microtile.
// ============================================================================
template<int ACT>  // 0 = none, 1 = gelu(exact erf)
__global__ __launch_bounds__(256)
void gemm_kernel(const float* __restrict__ A, const float* __restrict__ W,
                 const float* __restrict__ bias, float* __restrict__ C,
                 int M, int N, int K) {
    __shared__ float As[8][128];
    __shared__ float Bs[8][128];

    const int bm = blockIdx.y * 128;
    const int bn = blockIdx.x * 128;
    const int tid = threadIdx.x;
    const int tx = tid & 15;         // 0..15 -> N
    const int ty = tid >> 4;         // 0..15 -> M

    float acc[8][8];
#pragma unroll
    for (int i = 0; i < 8; i++)
#pragma unroll
        for (int j = 0; j < 8; j++) acc[i][j] = 0.f;

    const int lrow = tid >> 1;          // 0..127
    const int lk   = (tid & 1) * 4;     // 0 or 4
    const float* Aptr = A + (size_t)(bm + lrow) * K + lk;
    const float* Wptr = W + (size_t)(bn + lrow) * K + lk;

    for (int k0 = 0; k0 < K; k0 += 8) {
        float4 av = *(const float4*)(Aptr + k0);
        float4 wv = *(const float4*)(Wptr + k0);
        As[lk + 0][lrow] = av.x; As[lk + 1][lrow] = av.y;
        As[lk + 2][lrow] = av.z; As[lk + 3][lrow] = av.w;
        Bs[lk + 0][lrow] = wv.x; Bs[lk + 1][lrow] = wv.y;
        Bs[lk + 2][lrow] = wv.z; Bs[lk + 3][lrow] = wv.w;
        __syncthreads();

#pragma unroll
        for (int kk = 0; kk < 8; kk++) {
            float a[8], b[8];
#pragma unroll
            for (int i = 0; i < 8; i++) a[i] = As[kk][ty * 8 + i];
#pragma unroll
            for (int j = 0; j < 8; j++) b[j] = Bs[kk][tx * 8 + j];
#pragma unroll
            for (int i = 0; i < 8; i++)
#pragma unroll
                for (int j = 0; j < 8; j++)
                    acc[i][j] = fmaf(a[i], b[j], acc[i][j]);
        }
        __syncthreads();
    }

    // epilogue
    float bvals[8];
#pragma unroll
    for (int j = 0; j < 8; j++) bvals[j] = bias[bn + tx * 8 + j];

#pragma unroll
    for (int i = 0; i < 8; i++) {
        const int m = bm + ty * 8 + i;
        float* Crow = C + (size_t)m * N + bn + tx * 8;
        float4 o0, o1;
        float v[8];
#pragma unroll
        for (int j = 0; j < 8; j++) {
            float t = acc[i][j] + bvals[j];
            if (ACT == 1) t = 0.5f * t * (1.0f + erff(t * 0.70710678118654752f));
            v[j] = t;
        }
        o0.x = v[0]; o0.y = v[1]; o0.z = v[2]; o0.w = v[3];
        o1.x = v[4]; o1.y = v[5]; o1.z = v[6]; o1.w = v[7];
        *(float4*)(Crow + 0) = o0;
        *(float4*)(Crow + 4) = o1;
    }
}

// ============================================================================
// Flash attention: one block = one (q-tile of 64, head, batch).
// Q/K/V come from the fused qkv buffer (row = token, cols = h*192 + {0,64,128} + d).
// 256 threads as 16x16; each thread computes a 4x4 microtile of S and of ctx.
// Online softmax; P overwrites the K smem tile.
// ============================================================================
#define APAD 68

__global__ __launch_bounds__(256)
void attn_kernel(const float* __restrict__ qkv, float* __restrict__ ctx) {
    extern __shared__ float sm[];
    float* Qs  = sm;                   // 64 * APAD
    float* Ks  = Qs  + 64 * APAD;      // 64 * APAD  (reused for P)
    float* Vs  = Ks  + 64 * APAD;      // 64 * APAD
    float* red = Vs  + 64 * APAD;      // 64 * 16
    float* mrow = red + 64 * 16;       // 64
    float* lrow = mrow + 64;           // 64
    float* arow = lrow + 64;           // 64

    const int q0 = blockIdx.x * 64;
    const int h  = blockIdx.y;
    const int b  = blockIdx.z;
    const int tid = threadIdx.x;
    const int tx = tid & 15;
    const int ty = tid >> 4;

    const int LD = 3 * E_;             // 3072
    const float* base = qkv + (size_t)b * S_ * LD + h * (3 * HD_);

    // load Q tile (64 rows x 64 cols)
    {
        const int r  = tid >> 2;
        const int c0 = (tid & 3) * 16;
        const float* src = base + (size_t)(q0 + r) * LD + c0;
        float* dst = Qs + r * APAD + c0;
#pragma unroll
        for (int j = 0; j < 16; j += 4)
            *(float4*)(dst + j) = *(const float4*)(src + j);
    }
    if (tid < 64) { mrow[tid] = -1e30f; lrow[tid] = 0.f; }

    float acc[4][4];
#pragma unroll
    for (int i = 0; i < 4; i++)
#pragma unroll
        for (int j = 0; j < 4; j++) acc[i][j] = 0.f;

    for (int kt = 0; kt < S_ / 64; kt++) {
        const int k0 = kt * 64;
        __syncthreads();   // previous iter's P/V reads done before overwrite
        {
            const int r  = tid >> 2;
            const int c0 = (tid & 3) * 16;
            const float* srck = base + (size_t)(k0 + r) * LD + HD_ + c0;
            const float* srcv = base + (size_t)(k0 + r) * LD + 2 * HD_ + c0;
            float* dk = Ks + r * APAD + c0;
            float* dv = Vs + r * APAD + c0;
#pragma unroll
            for (int j = 0; j < 16; j += 4) {
                *(float4*)(dk + j) = *(const float4*)(srck + j);
                *(float4*)(dv + j) = *(const float4*)(srcv + j);
            }
        }
        __syncthreads();

        // S = (Q K^T) * 1/8
        float s[4][4];
#pragma unroll
        for (int i = 0; i < 4; i++)
#pragma unroll
            for (int j = 0; j < 4; j++) s[i][j] = 0.f;

        for (int d = 0; d < 64; d++) {
            float qv[4], kv[4];
#pragma unroll
            for (int i = 0; i < 4; i++) qv[i] = Qs[(ty * 4 + i) * APAD + d];
#pragma unroll
            for (int j = 0; j < 4; j++) kv[j] = Ks[(tx * 4 + j) * APAD + d];
#pragma unroll
            for (int i = 0; i < 4; i++)
#pragma unroll
                for (int j = 0; j < 4; j++)
                    s[i][j] = fmaf(qv[i], kv[j], s[i][j]);
        }
        const float scale = 0.125f;   // 1/sqrt(64)
#pragma unroll
        for (int i = 0; i < 4; i++)
#pragma unroll
            for (int j = 0; j < 4; j++) s[i][j] *= scale;

        // row max (per-thread, then across 16 tx threads)
#pragma unroll
        for (int i = 0; i < 4; i++) {
            float t = s[i][0];
#pragma unroll
            for (int j = 1; j < 4; j++) t = fmaxf(t, s[i][j]);
            red[(ty * 4 + i) * 16 + tx] = t;
        }
        __syncthreads();
        if (tid < 64) {
            float mx = red[tid * 16];
#pragma unroll
            for (int t = 1; t < 16; t++) mx = fmaxf(mx, red[tid * 16 + t]);
            float mold = mrow[tid];
            float mnew = fmaxf(mold, mx);
            mrow[tid] = mnew;
            arow[tid] = __expf(mold - mnew);
        }
        __syncthreads();

        // P = exp(S - m), rescale acc, partial row sums; P -> Ks
        float a_i[4], m_i[4], psum[4];
#pragma unroll
        for (int i = 0; i < 4; i++) {
            a_i[i] = arow[ty * 4 + i];
            m_i[i] = mrow[ty * 4 + i];
            psum[i] = 0.f;
        }
#pragma unroll
        for (int i = 0; i < 4; i++) {
#pragma unroll
            for (int j = 0; j < 4; j++) {
                float p = __expf(s[i][j] - m_i[i]);
                Ks[(ty * 4 + i) * APAD + tx * 4 + j] = p;
                psum[i] += p;
                acc[i][j] *= a_i[i];
            }
            red[(ty * 4 + i) * 16 + tx] = psum[i];
        }
        __syncthreads();
        if (tid < 64) {
            float ssum = 0.f;
#pragma unroll
            for (int t = 0; t < 16; t++) ssum += red[tid * 16 + t];
            lrow[tid] = lrow[tid] * arow[tid] + ssum;
        }

        // acc += P @ V  (Ks holds P)
        for (int kk = 0; kk < 64; kk++) {
            float pv[4], vv[4];
#pragma unroll
            for (int i = 0; i < 4; i++) pv[i] = Ks[(ty * 4 + i) * APAD + kk];
#pragma unroll
            for (int j = 0; j < 4; j++) vv[j] = Vs[kk * APAD + tx * 4 + j];
#pragma unroll
            for (int i = 0; i < 4; i++)
#pragma unroll
                for (int j = 0; j < 4; j++)
                    acc[i][j] = fmaf(pv[i], vv[j], acc[i][j]);
        }
    }
    __syncthreads();

    // epilogue: ctx[b, q0+r, h*64 + c] = acc / l
#pragma unroll
    for (int i = 0; i < 4; i++) {
        const int r = ty * 4 + i;
        const float linv = 1.0f / lrow[r];
        float* dst = ctx + ((size_t)b * S_ + q0 + r) * E_ + h * HD_ + tx * 4;
        float4 o;
        o.x = acc[i][0] * linv; o.y = acc[i][1] * linv;
        o.z = acc[i][2] * linv; o.w = acc[i][3] * linv;
        *(float4*)dst = o;
    }
}

// ============================================================================
// Fused residual-add + LayerNorm over E=1024. One block per row, 256 threads.
// ============================================================================
__global__ __launch_bounds__(256)
void add_ln_kernel(const float* __restrict__ x, const float* __restrict__ y,
                   const float* __restrict__ g, const float* __restrict__ beta,
                   float* __restrict__ out) {
    __shared__ float red1[8], red2[8];
    __shared__ float s_mean, s_rstd;
    const int row = blockIdx.x;
    const int tid = threadIdx.x;

    const float4 xv = ((const float4*)(x + (size_t)row * E_))[tid];
    const float4 yv = ((const float4*)(y + (size_t)row * E_))[tid];
    float v0 = xv.x + yv.x, v1 = xv.y + yv.y, v2 = xv.z + yv.z, v3 = xv.w + yv.w;

    float s  = v0 + v1 + v2 + v3;
    float ss = v0 * v0 + v1 * v1 + v2 * v2 + v3 * v3;
#pragma unroll
    for (int o = 16; o > 0; o >>= 1) {
        s  += __shfl_down_sync(0xffffffffu, s, o);
        ss += __shfl_down_sync(0xffffffffu, ss, o);
    }
    const int warp = tid >> 5, lane = tid & 31;
    if (lane == 0) { red1[warp] = s; red2[warp] = ss; }
    __syncthreads();
    if (tid == 0) {
        float ts = 0.f, tss = 0.f;
#pragma unroll
        for (int w = 0; w < 8; w++) { ts += red1[w]; tss += red2[w]; }
        float mean = ts * (1.0f / E_);
        float var  = tss * (1.0f / E_) - mean * mean;
        s_mean = mean;
        s_rstd = rsqrtf(var + 1e-5f);
    }
    __syncthreads();
    const float mean = s_mean, rstd = s_rstd;

    const float4 gv = ((const float4*)g)[tid];
    const float4 bv = ((const float4*)beta)[tid];
    float4 o;
    o.x = (v0 - mean) * rstd * gv.x + bv.x;
    o.y = (v1 - mean) * rstd * gv.y + bv.y;
    o.z = (v2 - mean) * rstd * gv.z + bv.z;
    o.w = (v3 - mean) * rstd * gv.w + bv.w;
    ((float4*)(out + (size_t)row * E_))[tid] = o;
}

// ============================================================================
// Launch
// ============================================================================
extern "C" void kernel_launch(void* const* d_in, const int* in_sizes, int n_in,
                              void* d_out, int out_size) {
    const float* x     = (const float*)d_in[0];
    const float* w_qkv = (const float*)d_in[1];
    const float* b_qkv = (const float*)d_in[2];
    const float* w_out = (const float*)d_in[3];
    const float* b_out = (const float*)d_in[4];
    const float* g1    = (const float*)d_in[5];
    const float* beta1 = (const float*)d_in[6];
    const float* g2    = (const float*)d_in[7];
    const float* beta2 = (const float*)d_in[8];
    const float* w1    = (const float*)d_in[9];
    const float* bf1   = (const float*)d_in[10];
    const float* w2    = (const float*)d_in[11];
    const float* bf2   = (const float*)d_in[12];
    float* out = (float*)d_out;

    float *qkv, *ctx, *tmp, *x1, *hbuf;
    cudaGetSymbolAddress((void**)&qkv,  g_qkv);
    cudaGetSymbolAddress((void**)&ctx,  g_ctx);
    cudaGetSymbolAddress((void**)&tmp,  g_tmp);
    cudaGetSymbolAddress((void**)&x1,   g_x1);
    cudaGetSymbolAddress((void**)&hbuf, g_h);

    const int attn_smem = (3 * 64 * APAD + 64 * 16 + 3 * 64) * (int)sizeof(float);
    cudaFuncSetAttribute(attn_kernel, cudaFuncAttributeMaxDynamicSharedMemorySize, attn_smem);

    dim3 thr(256);

    // 1) qkv = x @ w_qkv^T + b_qkv     [4096 x 3072], K=1024
    gemm_kernel<0><<<dim3(3 * E_ / 128, M_ / 128), thr>>>(x, w_qkv, b_qkv, qkv, M_, 3 * E_, E_);

    // 2) flash attention -> ctx  [4096 x 1024]
    attn_kernel<<<dim3(S_ / 64, H_, B_), thr, attn_smem>>>(qkv, ctx);

    // 3) attn_out = ctx @ w_out^T + b_out -> tmp; x1 = LN(x + tmp)
    gemm_kernel<0><<<dim3(E_ / 128, M_ / 128), thr>>>(ctx, w_out, b_out, tmp, M_, E_, E_);
    add_ln_kernel<<<M_, thr>>>(x, tmp, g1, beta1, x1);

    // 4) h = gelu(x1 @ w1^T + bf1)    [4096 x 4096], K=1024
    gemm_kernel<1><<<dim3(FF_ / 128, M_ / 128), thr>>>(x1, w1, bf1, hbuf, M_, FF_, E_);

    // 5) ffn = h @ w2^T + bf2 -> tmp; out = LN(x1 + tmp)
    gemm_kernel<0><<<dim3(E_ / 128, M_ / 128), thr>>>(hbuf, w2, bf2, tmp, M_, E_, FF_);
    add_ln_kernel<<<M_, thr>>>(x1, tmp, g2, beta2, out);
}